// round 2
// baseline (speedup 1.0000x reference)
#include <cuda_runtime.h>
#include <cuda_bf16.h>

// Problem constants: x[D,N] @ W*[N,D] + b*, scores = qk^T/sqrt(D), p = softmax(scores),
// out = p @ v^T.   D = N = 4096.
#define DIM 4096
constexpr float SM_SCALE = 0.015625f;  // 1/sqrt(4096) = 1/64

// Scratch (alloc-free rule: __device__ globals). 4 x 64 MB fp32.
__device__ float g_q[(size_t)DIM * DIM];
__device__ float g_k[(size_t)DIM * DIM];
__device__ float g_v[(size_t)DIM * DIM];
__device__ float g_s[(size_t)DIM * DIM];

// ---------------------------------------------------------------------------
// SGEMM: C[M,N] (+epilogue), M=N=K=4096.
//   TRANSB=0: C[i][j] = sum_k A[i][k] * B[k][j]   (B row-major [K,N])
//   TRANSB=1: C[i][j] = sum_k A[i][k] * B[j][k]   (B row-major [N,K])
//   EPI=0: + bias[j];  EPI=1: * SM_SCALE;  EPI=2: none
// BM=BN=128, BK=16, 256 threads, 8x8 per-thread micro-tile.
// ---------------------------------------------------------------------------
template <int TRANSB, int EPI>
__global__ __launch_bounds__(256, 2) void sgemm_kernel(
    const float* __restrict__ A, const float* __restrict__ B,
    const float* __restrict__ bias, float* __restrict__ C) {
  constexpr int K = DIM;
  constexpr int N = DIM;
  constexpr int PAD = 132;  // 132 % 32 == 4 -> breaks scatter-store conflicts

  __shared__ float As[16][PAD];
  __shared__ float Bs[16][PAD];

  const int tid = threadIdx.x;
  const int tx = tid & 15;        // 0..15 -> column group
  const int ty = tid >> 4;        // 0..15 -> row group
  const int rowBase = blockIdx.y * 128;
  const int colBase = blockIdx.x * 128;

  float acc[8][8];
#pragma unroll
  for (int i = 0; i < 8; i++)
#pragma unroll
    for (int j = 0; j < 8; j++) acc[i][j] = 0.0f;

  float a_frag[8], b_frag[8];

  for (int kt = 0; kt < K; kt += 16) {
    // ---- load A tile (128 rows x 16 k), transposed into As[k][r] ----
#pragma unroll
    for (int l = tid; l < 512; l += 256) {
      const int r = l >> 2;
      const int cg = l & 3;
      const float4 av = *reinterpret_cast<const float4*>(
          &A[(size_t)(rowBase + r) * K + kt + cg * 4]);
      As[cg * 4 + 0][r] = av.x;
      As[cg * 4 + 1][r] = av.y;
      As[cg * 4 + 2][r] = av.z;
      As[cg * 4 + 3][r] = av.w;
    }
    // ---- load B tile into Bs[k][j] ----
    if (TRANSB == 0) {
#pragma unroll
      for (int l = tid; l < 512; l += 256) {
        const int c = l >> 5;
        const int jg = l & 31;
        const float4 bv = *reinterpret_cast<const float4*>(
            &B[(size_t)(kt + c) * N + colBase + jg * 4]);
        *reinterpret_cast<float4*>(&Bs[c][jg * 4]) = bv;
      }
    } else {
#pragma unroll
      for (int l = tid; l < 512; l += 256) {
        const int j = l >> 2;
        const int cg = l & 3;
        const float4 bv = *reinterpret_cast<const float4*>(
            &B[(size_t)(colBase + j) * K + kt + cg * 4]);
        Bs[cg * 4 + 0][j] = bv.x;
        Bs[cg * 4 + 1][j] = bv.y;
        Bs[cg * 4 + 2][j] = bv.z;
        Bs[cg * 4 + 3][j] = bv.w;
      }
    }
    __syncthreads();

    // ---- compute 8x8 outer products over the 16 k-slices ----
#pragma unroll
    for (int c = 0; c < 16; c++) {
      *reinterpret_cast<float4*>(&a_frag[0]) =
          *reinterpret_cast<const float4*>(&As[c][ty * 8]);
      *reinterpret_cast<float4*>(&a_frag[4]) =
          *reinterpret_cast<const float4*>(&As[c][ty * 8 + 4]);
      *reinterpret_cast<float4*>(&b_frag[0]) =
          *reinterpret_cast<const float4*>(&Bs[c][tx * 8]);
      *reinterpret_cast<float4*>(&b_frag[4]) =
          *reinterpret_cast<const float4*>(&Bs[c][tx * 8 + 4]);
#pragma unroll
      for (int i = 0; i < 8; i++)
#pragma unroll
        for (int j = 0; j < 8; j++) acc[i][j] += a_frag[i] * b_frag[j];
    }
    __syncthreads();
  }

  // ---- epilogue ----
#pragma unroll
  for (int i = 0; i < 8; i++) {
    const int row = rowBase + ty * 8 + i;
#pragma unroll
    for (int j = 0; j < 8; j += 4) {
      const int col = colBase + tx * 8 + j;
      float4 o;
      o.x = acc[i][j + 0];
      o.y = acc[i][j + 1];
      o.z = acc[i][j + 2];
      o.w = acc[i][j + 3];
      if (EPI == 0) {
        o.x += bias[col + 0];
        o.y += bias[col + 1];
        o.z += bias[col + 2];
        o.w += bias[col + 3];
      } else if (EPI == 1) {
        o.x *= SM_SCALE;
        o.y *= SM_SCALE;
        o.z *= SM_SCALE;
        o.w *= SM_SCALE;
      }
      *reinterpret_cast<float4*>(&C[(size_t)row * N + col]) = o;
    }
  }
}

// ---------------------------------------------------------------------------
// Row softmax, in place. One block per row of 4096.
// ---------------------------------------------------------------------------
__global__ __launch_bounds__(256) void softmax_rows_kernel(float* __restrict__ S) {
  float* p = S + (size_t)blockIdx.x * DIM;
  const int tid = threadIdx.x;
  __shared__ float red[256];

  float m = -3.402823466e38f;
  for (int i = tid; i < DIM; i += 256) m = fmaxf(m, p[i]);
  red[tid] = m;
  __syncthreads();
  for (int s = 128; s > 0; s >>= 1) {
    if (tid < s) red[tid] = fmaxf(red[tid], red[tid + s]);
    __syncthreads();
  }
  m = red[0];
  __syncthreads();

  float sum = 0.0f;
  for (int i = tid; i < DIM; i += 256) {
    const float e = expf(p[i] - m);
    p[i] = e;
    sum += e;
  }
  red[tid] = sum;
  __syncthreads();
  for (int s = 128; s > 0; s >>= 1) {
    if (tid < s) red[tid] += red[tid + s];
    __syncthreads();
  }
  const float inv = 1.0f / red[0];
  for (int i = tid; i < DIM; i += 256) p[i] *= inv;
}

// ---------------------------------------------------------------------------
// Launch: q/k/v projections -> scores -> softmax -> p @ v^T
// Inputs (metadata order): x, Wq, bq, Wk, bk, Wv, bv
// ---------------------------------------------------------------------------
extern "C" void kernel_launch(void* const* d_in, const int* in_sizes, int n_in,
                              void* d_out, int out_size) {
  const float* x = (const float*)d_in[0];
  const float* Wq = (const float*)d_in[1];
  const float* bq = (const float*)d_in[2];
  const float* Wk = (const float*)d_in[3];
  const float* bk = (const float*)d_in[4];
  const float* Wv = (const float*)d_in[5];
  const float* bv = (const float*)d_in[6];
  float* out = (float*)d_out;

  float *q, *k, *v, *s;
  cudaGetSymbolAddress((void**)&q, g_q);
  cudaGetSymbolAddress((void**)&k, g_k);
  cudaGetSymbolAddress((void**)&v, g_v);
  cudaGetSymbolAddress((void**)&s, g_s);

  dim3 grid(DIM / 128, DIM / 128);
  dim3 block(256);

  // Projections (NN + bias)
  sgemm_kernel<0, 0><<<grid, block>>>(x, Wq, bq, q);
  sgemm_kernel<0, 0><<<grid, block>>>(x, Wk, bk, k);
  sgemm_kernel<0, 0><<<grid, block>>>(x, Wv, bv, v);
  // scores = q @ k^T * scale  (NT)
  sgemm_kernel<1, 1><<<grid, block>>>(q, k, nullptr, s);
  // softmax rows, in place
  softmax_rows_kernel<<<DIM, 256>>>(s);
  // out = p @ v^T  (NT)
  sgemm_kernel<1, 2><<<grid, block>>>(s, v, nullptr, out);
}

// round 4
// speedup vs baseline: 3.2418x; 3.2418x over previous
#include <cuda_runtime.h>
#include <cuda_bf16.h>
#include <cstdint>

#define DIM 4096
constexpr float SM_SCALE = 0.015625f;  // 1/sqrt(4096)
#define ELEMS ((size_t)DIM * (size_t)DIM)

// ---------------------------------------------------------------------------
// Scratch (__device__ globals; alloc-free rule).
// ---------------------------------------------------------------------------
__device__ __align__(1024) __nv_bfloat16 g_x_hi[ELEMS];
__device__ __align__(1024) __nv_bfloat16 g_x_lo[ELEMS];
__device__ __align__(1024) __nv_bfloat16 g_wqt_hi[ELEMS];
__device__ __align__(1024) __nv_bfloat16 g_wqt_lo[ELEMS];
__device__ __align__(1024) __nv_bfloat16 g_wkt_hi[ELEMS];
__device__ __align__(1024) __nv_bfloat16 g_wkt_lo[ELEMS];
__device__ __align__(1024) __nv_bfloat16 g_wvt_hi[ELEMS];
__device__ __align__(1024) __nv_bfloat16 g_wvt_lo[ELEMS];
__device__ __align__(1024) __nv_bfloat16 g_q_hi[ELEMS];
__device__ __align__(1024) __nv_bfloat16 g_q_lo[ELEMS];
__device__ __align__(1024) __nv_bfloat16 g_k_hi[ELEMS];
__device__ __align__(1024) __nv_bfloat16 g_k_lo[ELEMS];
__device__ __align__(1024) __nv_bfloat16 g_v_hi[ELEMS];
__device__ __align__(1024) __nv_bfloat16 g_v_lo[ELEMS];
__device__ __align__(1024) __nv_bfloat16 g_p_hi[ELEMS];
__device__ __align__(1024) __nv_bfloat16 g_p_lo[ELEMS];
__device__ __align__(1024) float g_s[ELEMS];

__device__ __forceinline__ uint32_t smem_u32(const void* p) {
  uint32_t a;
  asm("{ .reg .u64 t; cvta.to.shared.u64 t, %1; cvt.u32.u64 %0, t; }"
      : "=r"(a) : "l"(p));
  return a;
}
__device__ __forceinline__ uint32_t pack2(__nv_bfloat16 a, __nv_bfloat16 b) {
  return (uint32_t)__bfloat16_as_ushort(a) |
         ((uint32_t)__bfloat16_as_ushort(b) << 16);
}

#define CP16(s, g) \
  asm volatile("cp.async.cg.shared.global [%0], [%1], 16;" ::"r"(s), "l"(g))
#define CP_COMMIT() asm volatile("cp.async.commit_group;")
#define CP_WAIT1() asm volatile("cp.async.wait_group 1;")

#define LDSM4(r, addr)                                                       \
  asm volatile("ldmatrix.sync.aligned.m8n8.x4.shared.b16 {%0,%1,%2,%3}, [%4];" \
               : "=r"((r)[0]), "=r"((r)[1]), "=r"((r)[2]), "=r"((r)[3])      \
               : "r"(addr))

#define MMA16816(d, a, b0, b1)                                              \
  asm volatile(                                                             \
      "mma.sync.aligned.m16n8k16.row.col.f32.bf16.bf16.f32 "                \
      "{%0,%1,%2,%3},{%4,%5,%6,%7},{%8,%9},{%0,%1,%2,%3};"                  \
      : "+f"((d)[0]), "+f"((d)[1]), "+f"((d)[2]), "+f"((d)[3])              \
      : "r"((a)[0]), "r"((a)[1]), "r"((a)[2]), "r"((a)[3]), "r"(b0), "r"(b1))

// ---------------------------------------------------------------------------
// Split-bf16 GEMM: C[4096,4096] = A @ B^T, K=4096, both operands hi/lo bf16
// K-major. Tile 128x128, BK=64, 3-stage cp.async, 256 threads (8 warps 32x64).
// EPI 0: +bias -> hi/lo bf16 out. EPI 1: *SM_SCALE -> fp32. EPI 2: fp32.
// ---------------------------------------------------------------------------
#define NSTAGE 3
#define STB (64 * 1024)   // stage bytes: 4 operand tiles x 16KB
#define OPB (16 * 1024)   // one 128x64 bf16 tile
#define NK (DIM / 64)     // 64 k-stages

template <int EPI>
__global__ __launch_bounds__(256, 1) void gemm_mma(
    const __nv_bfloat16* __restrict__ Ah, const __nv_bfloat16* __restrict__ Al,
    const __nv_bfloat16* __restrict__ Bh, const __nv_bfloat16* __restrict__ Bl,
    const float* __restrict__ bias, float* __restrict__ outF,
    __nv_bfloat16* __restrict__ outH, __nv_bfloat16* __restrict__ outL) {
  extern __shared__ __align__(128) char dyn[];
  const uint32_t smem = smem_u32(dyn);

  const int tid = threadIdx.x;
  const int lane = tid & 31;
  const int wid = tid >> 5;
  const int wm = (wid & 3) * 32;   // warp M offset (4 warps down)
  const int wn = (wid >> 2) * 64;  // warp N offset (2 warps across)
  const int rowBase = blockIdx.y * 128;
  const int colBase = blockIdx.x * 128;

  // ldmatrix per-lane address components
  const int mat = lane >> 3, rin = lane & 7;
  const int aRow = (mat & 1) * 8 + rin;  // A: mats 0/1 rows, 2/3 k+8
  const int aC = mat >> 1;
  const int bRow = (mat >> 1) * 8 + rin;  // B: mats 0/1 k, k+8 of n0-7
  const int bC = mat & 1;

  float acc[2][8][4];
#pragma unroll
  for (int i = 0; i < 2; i++)
#pragma unroll
    for (int j = 0; j < 8; j++)
#pragma unroll
      for (int l = 0; l < 4; l++) acc[i][j][l] = 0.0f;

  // ---- stage loader: 4 tiles x 1024 16B-chunks, 16 cp.async per thread ----
  auto load_stage = [&](int kt, int st) {
    const uint32_t sb = smem + st * STB;
#pragma unroll
    for (int i = 0; i < 16; i++) {
      const int id = i * 256 + tid;
      const int o = id >> 10;
      const int r = (id >> 3) & 127;
      const int c = id & 7;
      const __nv_bfloat16* gb =
          (o == 0) ? Ah : (o == 1) ? Al : (o == 2) ? Bh : Bl;
      const int gRow = ((o < 2) ? rowBase : colBase) + r;
      const char* g =
          (const char*)gb + (size_t)gRow * (DIM * 2) + kt * 128 + c * 16;
      const uint32_t s = sb + o * OPB + r * 128 + ((c ^ (r & 7)) << 4);
      CP16(s, g);
    }
  };

  // prologue: 2 stages in flight
  load_stage(0, 0);
  CP_COMMIT();
  load_stage(1, 1);
  CP_COMMIT();

  for (int kt = 0; kt < NK; kt++) {
    CP_WAIT1();
    __syncthreads();
    // issue next-next stage (slot freed by last iteration's consumers)
    if (kt + 2 < NK) load_stage(kt + 2, (kt + 2) % NSTAGE);
    CP_COMMIT();

    const uint32_t sb = smem + (kt % NSTAGE) * STB;
    const uint32_t sAh = sb;
    const uint32_t sBh = sb + 2 * OPB;
#pragma unroll
    for (int ks = 0; ks < 4; ks++) {
      uint32_t ah[2][4], al[2][4], bh[4][4], bl[4][4];
#pragma unroll
      for (int mi = 0; mi < 2; mi++) {
        const int row = wm + mi * 16 + aRow;
        const int c = ks * 2 + aC;
        const uint32_t ad = sAh + row * 128 + ((c ^ rin) << 4);
        LDSM4(ah[mi], ad);
        LDSM4(al[mi], ad + OPB);
      }
#pragma unroll
      for (int g = 0; g < 4; g++) {
        const int row = wn + g * 16 + bRow;
        const int c = ks * 2 + bC;
        const uint32_t bd = sBh + row * 128 + ((c ^ rin) << 4);
        LDSM4(bh[g], bd);
        LDSM4(bl[g], bd + OPB);
      }
#pragma unroll
      for (int mi = 0; mi < 2; mi++)
#pragma unroll
        for (int g = 0; g < 4; g++) {
          MMA16816(acc[mi][2 * g + 0], ah[mi], bh[g][0], bh[g][1]);
          MMA16816(acc[mi][2 * g + 1], ah[mi], bh[g][2], bh[g][3]);
          MMA16816(acc[mi][2 * g + 0], ah[mi], bl[g][0], bl[g][1]);
          MMA16816(acc[mi][2 * g + 1], ah[mi], bl[g][2], bl[g][3]);
          MMA16816(acc[mi][2 * g + 0], al[mi], bh[g][0], bh[g][1]);
          MMA16816(acc[mi][2 * g + 1], al[mi], bh[g][2], bh[g][3]);
        }
    }
  }

  // ---- epilogue ----
  const int r0b = rowBase + wm + (lane >> 2);
  const int c0b = colBase + wn + (lane & 3) * 2;
#pragma unroll
  for (int mi = 0; mi < 2; mi++) {
#pragma unroll
    for (int nb = 0; nb < 8; nb++) {
      const int col = c0b + nb * 8;
      const int row0 = r0b + mi * 16;
      const int row1 = row0 + 8;
      const float* a = acc[mi][nb];
      if (EPI == 0) {
        const float b0v = __ldg(&bias[col]);
        const float b1v = __ldg(&bias[col + 1]);
        const float v0 = a[0] + b0v, v1 = a[1] + b1v;
        const float v2 = a[2] + b0v, v3 = a[3] + b1v;
        const __nv_bfloat16 h0 = __float2bfloat16(v0),
                            h1 = __float2bfloat16(v1);
        const __nv_bfloat16 h2 = __float2bfloat16(v2),
                            h3 = __float2bfloat16(v3);
        *reinterpret_cast<uint32_t*>(&outH[(size_t)row0 * DIM + col]) =
            pack2(h0, h1);
        *reinterpret_cast<uint32_t*>(&outH[(size_t)row1 * DIM + col]) =
            pack2(h2, h3);
        *reinterpret_cast<uint32_t*>(&outL[(size_t)row0 * DIM + col]) =
            pack2(__float2bfloat16(v0 - __bfloat162float(h0)),
                  __float2bfloat16(v1 - __bfloat162float(h1)));
        *reinterpret_cast<uint32_t*>(&outL[(size_t)row1 * DIM + col]) =
            pack2(__float2bfloat16(v2 - __bfloat162float(h2)),
                  __float2bfloat16(v3 - __bfloat162float(h3)));
      } else {
        const float s = (EPI == 1) ? SM_SCALE : 1.0f;
        *reinterpret_cast<float2*>(&outF[(size_t)row0 * DIM + col]) =
            make_float2(a[0] * s, a[1] * s);
        *reinterpret_cast<float2*>(&outF[(size_t)row1 * DIM + col]) =
            make_float2(a[2] * s, a[3] * s);
      }
    }
  }
}

// ---------------------------------------------------------------------------
// Elementwise split: fp32 -> (hi, lo) bf16.
// ---------------------------------------------------------------------------
__global__ __launch_bounds__(256) void split_plain(
    const float4* __restrict__ in, uint2* __restrict__ h,
    uint2* __restrict__ l) {
  const size_t i = (size_t)blockIdx.x * 256 + threadIdx.x;
  const float4 v = in[i];
  const __nv_bfloat16 h0 = __float2bfloat16(v.x), h1 = __float2bfloat16(v.y);
  const __nv_bfloat16 h2 = __float2bfloat16(v.z), h3 = __float2bfloat16(v.w);
  h[i] = make_uint2(pack2(h0, h1), pack2(h2, h3));
  l[i] = make_uint2(pack2(__float2bfloat16(v.x - __bfloat162float(h0)),
                          __float2bfloat16(v.y - __bfloat162float(h1))),
                    pack2(__float2bfloat16(v.z - __bfloat162float(h2)),
                          __float2bfloat16(v.w - __bfloat162float(h3))));
}

// ---------------------------------------------------------------------------
// Transpose + split: W fp32 -> Wt hi/lo bf16 (Wt[r][c] = W[c][r]).
// ---------------------------------------------------------------------------
__global__ __launch_bounds__(1024) void transpose_split(
    const float* __restrict__ W, __nv_bfloat16* __restrict__ th,
    __nv_bfloat16* __restrict__ tl) {
  __shared__ float t[32][33];
  const int bx = blockIdx.x * 32, by = blockIdx.y * 32;
  const int x = threadIdx.x & 31, y = threadIdx.x >> 5;
  t[y][x] = W[(size_t)(by + y) * DIM + bx + x];
  __syncthreads();
  const float v = t[x][y];
  const __nv_bfloat16 h = __float2bfloat16(v);
  const size_t o = (size_t)(bx + y) * DIM + by + x;
  th[o] = h;
  tl[o] = __float2bfloat16(v - __bfloat162float(h));
}

// ---------------------------------------------------------------------------
// Row softmax: fp32 scores -> p (hi, lo) bf16. 256 threads per row.
// ---------------------------------------------------------------------------
__global__ __launch_bounds__(256) void softmax_split(
    const float* __restrict__ S, __nv_bfloat16* __restrict__ ph,
    __nv_bfloat16* __restrict__ pl) {
  const int row = blockIdx.x;
  const float4* src = reinterpret_cast<const float4*>(S + (size_t)row * DIM);
  const int tid = threadIdx.x;
  float v[16];
#pragma unroll
  for (int i = 0; i < 4; i++) {
    const float4 t = src[i * 256 + tid];
    v[i * 4 + 0] = t.x; v[i * 4 + 1] = t.y;
    v[i * 4 + 2] = t.z; v[i * 4 + 3] = t.w;
  }
  float m = v[0];
#pragma unroll
  for (int i = 1; i < 16; i++) m = fmaxf(m, v[i]);
  __shared__ float red[8];
#pragma unroll
  for (int o = 16; o > 0; o >>= 1) m = fmaxf(m, __shfl_xor_sync(~0u, m, o));
  if ((tid & 31) == 0) red[tid >> 5] = m;
  __syncthreads();
  m = red[0];
#pragma unroll
  for (int w = 1; w < 8; w++) m = fmaxf(m, red[w]);

  float sum = 0.f;
#pragma unroll
  for (int i = 0; i < 16; i++) {
    v[i] = __expf(v[i] - m);
    sum += v[i];
  }
#pragma unroll
  for (int o = 16; o > 0; o >>= 1) sum += __shfl_xor_sync(~0u, sum, o);
  __syncthreads();
  if ((tid & 31) == 0) red[tid >> 5] = sum;
  __syncthreads();
  sum = 0.f;
#pragma unroll
  for (int w = 0; w < 8; w++) sum += red[w];
  const float inv = 1.0f / sum;

  uint2* hdst = reinterpret_cast<uint2*>(ph + (size_t)row * DIM);
  uint2* ldst = reinterpret_cast<uint2*>(pl + (size_t)row * DIM);
#pragma unroll
  for (int i = 0; i < 4; i++) {
    const float p0 = v[i * 4 + 0] * inv, p1 = v[i * 4 + 1] * inv;
    const float p2 = v[i * 4 + 2] * inv, p3 = v[i * 4 + 3] * inv;
    const __nv_bfloat16 h0 = __float2bfloat16(p0), h1 = __float2bfloat16(p1);
    const __nv_bfloat16 h2 = __float2bfloat16(p2), h3 = __float2bfloat16(p3);
    hdst[i * 256 + tid] = make_uint2(pack2(h0, h1), pack2(h2, h3));
    ldst[i * 256 + tid] =
        make_uint2(pack2(__float2bfloat16(p0 - __bfloat162float(h0)),
                         __float2bfloat16(p1 - __bfloat162float(h1))),
                   pack2(__float2bfloat16(p2 - __bfloat162float(h2)),
                         __float2bfloat16(p3 - __bfloat162float(h3))));
  }
}

// ---------------------------------------------------------------------------
// Launch
// ---------------------------------------------------------------------------
extern "C" void kernel_launch(void* const* d_in, const int* in_sizes, int n_in,
                              void* d_out, int out_size) {
  const float* x = (const float*)d_in[0];
  const float* Wq = (const float*)d_in[1];
  const float* bq = (const float*)d_in[2];
  const float* Wk = (const float*)d_in[3];
  const float* bk = (const float*)d_in[4];
  const float* Wv = (const float*)d_in[5];
  const float* bv = (const float*)d_in[6];
  float* out = (float*)d_out;

  void *xh, *xl, *wqh, *wql, *wkh, *wkl, *wvh, *wvl;
  void *qh, *ql, *kh, *kl, *vh, *vl, *pph, *ppl, *sf;
  cudaGetSymbolAddress(&xh, g_x_hi);    cudaGetSymbolAddress(&xl, g_x_lo);
  cudaGetSymbolAddress(&wqh, g_wqt_hi); cudaGetSymbolAddress(&wql, g_wqt_lo);
  cudaGetSymbolAddress(&wkh, g_wkt_hi); cudaGetSymbolAddress(&wkl, g_wkt_lo);
  cudaGetSymbolAddress(&wvh, g_wvt_hi); cudaGetSymbolAddress(&wvl, g_wvt_lo);
  cudaGetSymbolAddress(&qh, g_q_hi);    cudaGetSymbolAddress(&ql, g_q_lo);
  cudaGetSymbolAddress(&kh, g_k_hi);    cudaGetSymbolAddress(&kl, g_k_lo);
  cudaGetSymbolAddress(&vh, g_v_hi);    cudaGetSymbolAddress(&vl, g_v_lo);
  cudaGetSymbolAddress(&pph, g_p_hi);   cudaGetSymbolAddress(&ppl, g_p_lo);
  cudaGetSymbolAddress(&sf, g_s);

  const int dynSmem = NSTAGE * STB;
  cudaFuncSetAttribute(gemm_mma<0>, cudaFuncAttributeMaxDynamicSharedMemorySize,
                       dynSmem);
  cudaFuncSetAttribute(gemm_mma<1>, cudaFuncAttributeMaxDynamicSharedMemorySize,
                       dynSmem);
  cudaFuncSetAttribute(gemm_mma<2>, cudaFuncAttributeMaxDynamicSharedMemorySize,
                       dynSmem);

  // 1) conversions
  split_plain<<<ELEMS / 4 / 256, 256>>>((const float4*)x, (uint2*)xh,
                                        (uint2*)xl);
  dim3 tg(DIM / 32, DIM / 32);
  transpose_split<<<tg, 1024>>>(Wq, (__nv_bfloat16*)wqh, (__nv_bfloat16*)wql);
  transpose_split<<<tg, 1024>>>(Wk, (__nv_bfloat16*)wkh, (__nv_bfloat16*)wkl);
  transpose_split<<<tg, 1024>>>(Wv, (__nv_bfloat16*)wvh, (__nv_bfloat16*)wvl);

  // 2) projections (bias -> hi/lo bf16)
  dim3 gg(DIM / 128, DIM / 128);
  gemm_mma<0><<<gg, 256, dynSmem>>>(
      (__nv_bfloat16*)xh, (__nv_bfloat16*)xl, (__nv_bfloat16*)wqh,
      (__nv_bfloat16*)wql, bq, nullptr, (__nv_bfloat16*)qh, (__nv_bfloat16*)ql);
  gemm_mma<0><<<gg, 256, dynSmem>>>(
      (__nv_bfloat16*)xh, (__nv_bfloat16*)xl, (__nv_bfloat16*)wkh,
      (__nv_bfloat16*)wkl, bk, nullptr, (__nv_bfloat16*)kh, (__nv_bfloat16*)kl);
  gemm_mma<0><<<gg, 256, dynSmem>>>(
      (__nv_bfloat16*)xh, (__nv_bfloat16*)xl, (__nv_bfloat16*)wvh,
      (__nv_bfloat16*)wvl, bv, nullptr, (__nv_bfloat16*)vh, (__nv_bfloat16*)vl);
  // 3) scores = q @ k^T * scale
  gemm_mma<1><<<gg, 256, dynSmem>>>(
      (__nv_bfloat16*)qh, (__nv_bfloat16*)ql, (__nv_bfloat16*)kh,
      (__nv_bfloat16*)kl, nullptr, (float*)sf, nullptr, nullptr);
  // 4) softmax -> p hi/lo
  softmax_split<<<DIM, 256>>>((const float*)sf, (__nv_bfloat16*)pph,
                              (__nv_bfloat16*)ppl);
  // 5) out = p @ v^T
  gemm_mma<2><<<gg, 256, dynSmem>>>(
      (__nv_bfloat16*)pph, (__nv_bfloat16*)ppl, (__nv_bfloat16*)vh,
      (__nv_bfloat16*)vl, nullptr, out, nullptr, nullptr);
}